// round 1
// baseline (speedup 1.0000x reference)
#include <cuda_runtime.h>

// BasicRNN: B=128 batches, S=8000 steps, H=64 hidden.
// One block per batch. 160 threads = 4 recurrence warps (thread pair per row)
// + 1 fc/readout warp pipelined one step behind.

#define BATCH 128
#define SEQ   8000
#define HID   64
#define CHUNK 800
#define NCHUNK (SEQ / CHUNK)   // 10
#define NTHREADS 160

__device__ __forceinline__ float tanh_fast(float z) {
    // 1 - 2/(exp(2z)+1): EX2 + RCP based, ~1e-6 abs error, handles +-inf
    float e = __expf(2.0f * z);
    return 1.0f - __fdividef(2.0f, e + 1.0f);
}

__device__ __forceinline__ float sigmoid_fast(float z) {
    return __fdividef(1.0f, 1.0f + __expf(-z));
}

__global__ void __launch_bounds__(NTHREADS, 1)
rnn_kernel(const float* __restrict__ x,      // [B, S]
           const float* __restrict__ W_ih,   // [H, 1]
           const float* __restrict__ b_ih,   // [H]
           const float* __restrict__ W_hh,   // [H, H]
           const float* __restrict__ b_hh,   // [H]
           const float* __restrict__ fc_w,   // [2, H]
           const float* __restrict__ fc_b,   // [2]
           float* __restrict__ out)          // [B]
{
    __shared__ float hb[2][HID];   // double-buffered hidden state
    __shared__ float xs[CHUNK];    // staged x chunk

    const int b    = blockIdx.x;
    const int tid  = threadIdx.x;
    const int lane = tid & 31;
    const bool rec = (tid < 128);
    const int r    = tid >> 1;     // row 0..63 (rec threads)
    const int half = tid & 1;      // which 32-wide half of h this lane covers

    // --- per-thread constants ---
    float w[32];                   // recurrence weights (registers)
    float wih_r = 0.f, bias_r = 0.f;
    float f0a = 0.f, f0b = 0.f, f1a = 0.f, f1b = 0.f, fb0 = 0.f, fb1 = 0.f;

    if (rec) {
        const float4* wp = (const float4*)(W_hh + r * HID + half * 32);
        #pragma unroll
        for (int i = 0; i < 8; i++) {
            float4 v = wp[i];
            w[4*i+0] = v.x; w[4*i+1] = v.y; w[4*i+2] = v.z; w[4*i+3] = v.w;
        }
        wih_r  = W_ih[r];
        bias_r = b_ih[r] + b_hh[r];
    } else {
        f0a = fc_w[lane];       f0b = fc_w[32 + lane];
        f1a = fc_w[64 + lane];  f1b = fc_w[96 + lane];
        fb0 = fc_b[0];          fb1 = fc_b[1];
    }

    // h_0 = 0
    if (tid < HID) hb[0][tid] = 0.0f;

    const float* xb = x + (long)b * SEQ;
    float num = 0.f, den = 0.f;

    int cur = 0;
    for (int c = 0; c < NCHUNK; ++c) {
        // stage x chunk (coalesced)
        for (int i = tid; i < CHUNK; i += NTHREADS)
            xs[i] = xb[c * CHUNK + i];
        __syncthreads();

        #pragma unroll 2
        for (int s = 0; s < CHUNK; ++s) {
            if (rec) {
                // h_{t+1}[r] = tanh(x_t*wih[r] + bias[r] + W_hh[r,:] . h_t)
                float xt = xs[s];
                float a0 = half ? 0.0f : fmaf(xt, wih_r, bias_r);
                float a1 = 0.f, a2 = 0.f, a3 = 0.f;
                const float4* h4 = (const float4*)(&hb[cur][half * 32]);
                #pragma unroll
                for (int i = 0; i < 8; i++) {
                    float4 hv = h4[i];
                    a0 = fmaf(w[4*i+0], hv.x, a0);
                    a1 = fmaf(w[4*i+1], hv.y, a1);
                    a2 = fmaf(w[4*i+2], hv.z, a2);
                    a3 = fmaf(w[4*i+3], hv.w, a3);
                }
                float sum = (a0 + a1) + (a2 + a3);
                float oth = __shfl_xor_sync(0xffffffffu, sum, 1);
                float hn  = tanh_fast(sum + oth);
                if (half == 0) hb[cur ^ 1][r] = hn;
            } else {
                // fc readout on h_t (previous step's result), pipelined
                float hA = hb[cur][lane];
                float hB = hb[cur][32 + lane];
                float p0 = fmaf(f0a, hA, f0b * hB);
                float p1 = fmaf(f1a, hA, f1b * hB);
                #pragma unroll
                for (int o = 16; o > 0; o >>= 1) {
                    p0 += __shfl_xor_sync(0xffffffffu, p0, o);
                    p1 += __shfl_xor_sync(0xffffffffu, p1, o);
                }
                float sel = sigmoid_fast(p0 + fb0);
                float sc  = sigmoid_fast(p1 + fb1);
                bool first = (c == 0 && s == 0);   // h_0 is not an output
                if (!first) { den += sel; num += sc * sel; }
            }
            __syncthreads();
            cur ^= 1;
        }
    }

    // tail: process h_S (sits in hb[cur] after the last swap)
    if (!rec) {
        float hA = hb[cur][lane];
        float hB = hb[cur][32 + lane];
        float p0 = fmaf(f0a, hA, f0b * hB);
        float p1 = fmaf(f1a, hA, f1b * hB);
        #pragma unroll
        for (int o = 16; o > 0; o >>= 1) {
            p0 += __shfl_xor_sync(0xffffffffu, p0, o);
            p1 += __shfl_xor_sync(0xffffffffu, p1, o);
        }
        float sel = sigmoid_fast(p0 + fb0);
        float sc  = sigmoid_fast(p1 + fb1);
        den += sel; num += sc * sel;
        if (lane == 0) out[b] = __fdividef(num, den);
    }
}

extern "C" void kernel_launch(void* const* d_in, const int* in_sizes, int n_in,
                              void* d_out, int out_size) {
    const float* x    = (const float*)d_in[0];
    const float* W_ih = (const float*)d_in[1];
    const float* b_ih = (const float*)d_in[2];
    const float* W_hh = (const float*)d_in[3];
    const float* b_hh = (const float*)d_in[4];
    const float* fc_w = (const float*)d_in[5];
    const float* fc_b = (const float*)d_in[6];
    float* out = (float*)d_out;
    (void)in_sizes; (void)n_in; (void)out_size;

    rnn_kernel<<<BATCH, NTHREADS>>>(x, W_ih, b_ih, W_hh, b_hh, fc_w, fc_b, out);
}